// round 5
// baseline (speedup 1.0000x reference)
#include <cuda_runtime.h>
#include <math_constants.h>

#define BS   1024
#define DM   512
#define NH   8
#define DK   64
#define HIST 199
#define TT   200
#define TTILE 8
#define NTILES 25

// Scratch (static device allocation is allowed)
__device__ float g_q[BS * DM];        // 2 MB
__device__ float g_r[BS * NH * DM];   // 16 MB
__device__ float g_c[BS * NH * DM];   // 16 MB

typedef unsigned long long u64;

// ---- packed f32x2 helpers --------------------------------------------------
__device__ __forceinline__ u64 pack2(float x, float y) {
    u64 r; asm("mov.b64 %0, {%1, %2};" : "=l"(r) : "f"(x), "f"(y)); return r;
}
__device__ __forceinline__ float2 unpack2(u64 v) {
    float2 d; asm("mov.b64 {%0, %1}, %2;" : "=f"(d.x), "=f"(d.y) : "l"(v)); return d;
}
__device__ __forceinline__ void ffma2(u64& acc, u64 a, u64 b) {
    asm("fma.rn.f32x2 %0, %1, %2, %0;" : "+l"(acc) : "l"(a), "l"(b));
}
__device__ __forceinline__ void fmul2(u64& a, u64 b) {
    asm("mul.rn.f32x2 %0, %0, %1;" : "+l"(a) : "l"(b));
}
__device__ __forceinline__ void cp16(void* smem_dst, const void* gsrc) {
    unsigned s = (unsigned)__cvta_generic_to_shared(smem_dst);
    asm volatile("cp.async.cg.shared.global [%0], [%1], 16;" :: "r"(s), "l"(gsrc));
}
__device__ __forceinline__ void cp_commit() { asm volatile("cp.async.commit_group;"); }
__device__ __forceinline__ void cp_wait0()  { asm volatile("cp.async.wait_group 0;"); }

// ============================================================================
// Kernel A: q = current @ Wq^T + bq      [1024,512] x [512,512] (NT)
// CTA: 32b x 64i tile, K-chunks of 64. 256 threads, 2x4 micro-tiles. grid 256.
// ============================================================================
__global__ void __launch_bounds__(256) k_qproj(
    const float* __restrict__ X, const float* __restrict__ Wq,
    const float* __restrict__ bq)
{
    __shared__ __align__(16) float Xs[32][64];
    __shared__ __align__(16) float Ws[64][68];   // transposed [k][i], padded
    const int tid = threadIdx.x;
    const int bB = blockIdx.x * 32;
    const int iB = blockIdx.y * 64;
    const int i0 = (tid & 15) * 4;
    const int b0 = (tid >> 4) * 2;

    u64 acc[2][2];
#pragma unroll
    for (int a = 0; a < 2; a++) { acc[a][0] = 0ull; acc[a][1] = 0ull; }

    for (int kc = 0; kc < 8; kc++) {
#pragma unroll
        for (int it = 0; it < 2; it++) {
            int idx = tid + 256 * it;                 // 512 float4
            int r = idx >> 4, c4 = (idx & 15) * 4;
            *(float4*)&Xs[r][c4] = *(const float4*)&X[(bB + r) * 512 + kc * 64 + c4];
        }
#pragma unroll
        for (int it = 0; it < 4; it++) {
            int idx = tid + 256 * it;                 // 1024 float4
            int r = idx >> 4, c4 = (idx & 15) * 4;
            float4 wv = *(const float4*)&Wq[(iB + r) * 512 + kc * 64 + c4];
            Ws[c4 + 0][r] = wv.x; Ws[c4 + 1][r] = wv.y;
            Ws[c4 + 2][r] = wv.z; Ws[c4 + 3][r] = wv.w;
        }
        __syncthreads();
#pragma unroll
        for (int k = 0; k < 64; k++) {
            ulonglong2 w2 = *(const ulonglong2*)&Ws[k][i0];
#pragma unroll
            for (int cb = 0; cb < 2; cb++) {
                float x = Xs[b0 + cb][k];
                u64 xx = pack2(x, x);
                ffma2(acc[cb][0], xx, w2.x);
                ffma2(acc[cb][1], xx, w2.y);
            }
        }
        __syncthreads();
    }
    float4 bqv = *(const float4*)&bq[iB + i0];
#pragma unroll
    for (int cb = 0; cb < 2; cb++) {
        float2 p0 = unpack2(acc[cb][0]);
        float2 p1 = unpack2(acc[cb][1]);
        float4 o = make_float4(p0.x + bqv.x, p0.y + bqv.y, p1.x + bqv.z, p1.y + bqv.w);
        *(float4*)&g_q[(bB + b0 + cb) * 512 + iB + i0] = o;
    }
}

// ============================================================================
// Kernel B: r[b,h,n] = sum_k q[b, h*64+k] * Wk[h*64+k, n]   (NN, K=64)
// ============================================================================
__global__ void __launch_bounds__(256) k_rproj(const float* __restrict__ Wk)
{
    __shared__ __align__(16) float Wks[64][128];
    __shared__ __align__(16) float qs[32][64];
    const int tid = threadIdx.x;
    const int nc = blockIdx.x;           // 0..3  (n chunk of 128)
    const int bB = blockIdx.y * 32;      // 0..31 (b tile of 32)
    const int h  = blockIdx.z;           // 0..7

#pragma unroll
    for (int it = 0; it < 8; it++) {
        int idx = tid + 256 * it;        // 2048 float4
        int k = idx >> 5, n4 = (idx & 31) * 4;
        *(float4*)&Wks[k][n4] = *(const float4*)&Wk[(h * 64 + k) * 512 + nc * 128 + n4];
    }
#pragma unroll
    for (int it = 0; it < 2; it++) {
        int idx = tid + 256 * it;        // 512 float4
        int bb = idx >> 4, k4 = (idx & 15) * 4;
        *(float4*)&qs[bb][k4] = *(const float4*)&g_q[(bB + bb) * 512 + h * 64 + k4];
    }
    __syncthreads();

    const int n0 = (tid & 31) * 4;
    const int b0 = (tid >> 5) * 4;
    u64 acc[4][2];
#pragma unroll
    for (int a = 0; a < 4; a++) { acc[a][0] = 0ull; acc[a][1] = 0ull; }

#pragma unroll
    for (int k = 0; k < 64; k++) {
        ulonglong2 w2 = *(const ulonglong2*)&Wks[k][n0];
#pragma unroll
        for (int cb = 0; cb < 4; cb++) {
            float x = qs[b0 + cb][k];
            u64 xx = pack2(x, x);
            ffma2(acc[cb][0], xx, w2.x);
            ffma2(acc[cb][1], xx, w2.y);
        }
    }
#pragma unroll
    for (int cb = 0; cb < 4; cb++) {
        float2 p0 = unpack2(acc[cb][0]), p1 = unpack2(acc[cb][1]);
        float4 o = make_float4(p0.x, p0.y, p1.x, p1.y);
        *(float4*)&g_r[((bB + b0 + cb) * 8 + h) * 512 + nc * 128 + n0] = o;
    }
}

// ============================================================================
// Kernel C: streaming attention, online softmax, softmax replicated per-lane.
// 1 CTA / batch row, 256 thr. Warp w owns j-slice [w*64,w*64+64); lane
// (h=l>>2, g=l&3) owns 16 j's of head h. Per 8-timestep tile: 2 syncs.
// ============================================================================
__device__ __forceinline__ void prefetch_tile(
    float* dst, const float* __restrict__ prev, const float* __restrict__ cur,
    int b, int tile, int tid)
{
#pragma unroll
    for (int i = 0; i < 4; i++) {
        int idx = tid + 256 * i;        // 1024 float4 = 8 rows x 512 floats
        int tr = idx >> 7;
        int c = (idx & 127) * 4;
        int gt = tile * TTILE + tr;
        const float* src = (gt < HIST)
            ? (prev + ((long)b * HIST + gt) * 512 + c)
            : (cur + (long)b * 512 + c);
        cp16(dst + tr * 512 + c, src);
    }
}

__global__ void __launch_bounds__(256) k_attn(
    const float* __restrict__ cur, const float* __restrict__ prev,
    const float* __restrict__ mask, const float* __restrict__ bk)
{
    __shared__ __align__(16) float xb[2][TTILE][DM];    // 32 KB
    __shared__ __align__(16) float s_part[8][8][TTILE]; // 2 KB
    __shared__ float mask_s[TT];
    __shared__ float sb_s[8];

    const int tid = threadIdx.x;
    const int b = blockIdx.x;
    const int w = tid >> 5, lane = tid & 31;
    const int h = lane >> 2, g = lane & 3;

    if (tid < TT) mask_s[tid] = mask[b * TT + tid];
    {   // sb[h] = q[b,h,:]·bk[h,:]; warp w handles head w
        float q1 = g_q[b * 512 + w * 64 + lane];
        float q2 = g_q[b * 512 + w * 64 + 32 + lane];
        float s = q1 * bk[w * 64 + lane] + q2 * bk[w * 64 + 32 + lane];
#pragma unroll
        for (int o = 16; o; o >>= 1) s += __shfl_xor_sync(0xffffffffu, s, o);
        if (lane == 0) sb_s[w] = s;
    }

    // r fragment straight from gmem (no smem staging)
    u64 rf[8];
    {
        const float4* rp = (const float4*)&g_r[(long)b * 4096 + h * 512 + w * 64 + g * 16];
#pragma unroll
        for (int i = 0; i < 4; i++) {
            float4 v = rp[i];
            rf[2 * i + 0] = pack2(v.x, v.y);
            rf[2 * i + 1] = pack2(v.z, v.w);
        }
    }
    u64 acc[8];
#pragma unroll
    for (int i = 0; i < 8; i++) acc[i] = 0ull;
    float m = -CUDART_INF_F, l = 0.f;

    prefetch_tile(&xb[0][0][0], prev, cur, b, 0, tid);
    cp_commit();
    __syncthreads();                       // sb_s / mask_s visible
    const float sb = sb_s[h];

    for (int tile = 0; tile < NTILES; tile++) {
        const int buf = tile & 1;
        cp_wait0();
        __syncthreads();                   // tile data visible CTA-wide

        const float* xbase = &xb[buf][0][w * 64 + g * 16];
        // ---- partial scores (x read once per warp-slice) ----
#pragma unroll
        for (int t = 0; t < TTILE; t++) {
            const u64* xp = (const u64*)(xbase + t * DM);
            u64 s2 = 0ull;
#pragma unroll
            for (int i = 0; i < 8; i++) ffma2(s2, rf[i], xp[i]);
            float2 sf = unpack2(s2);
            float s = sf.x + sf.y;
            s += __shfl_xor_sync(0xffffffffu, s, 1);
            s += __shfl_xor_sync(0xffffffffu, s, 2);
            if (g == 0) s_part[w][h][t] = s;
        }
        __syncthreads();                   // s_part complete

        // overlap next tile's load with softmax + accumulate
        if (tile + 1 < NTILES) {
            prefetch_tile(&xb[buf ^ 1][0][0], prev, cur, b, tile + 1, tid);
            cp_commit();
        }

        // ---- per-lane replicated online softmax for head h ----
        float4 a0 = make_float4(0.f, 0.f, 0.f, 0.f);
        float4 a1 = make_float4(0.f, 0.f, 0.f, 0.f);
#pragma unroll
        for (int w2 = 0; w2 < 8; w2++) {
            float4 v0 = *(const float4*)&s_part[w2][h][0];
            float4 v1 = *(const float4*)&s_part[w2][h][4];
            a0.x += v0.x; a0.y += v0.y; a0.z += v0.z; a0.w += v0.w;
            a1.x += v1.x; a1.y += v1.y; a1.z += v1.z; a1.w += v1.w;
        }
        const float* mk = &mask_s[tile * TTILE];
        float lg[8];
        lg[0] = (a0.x + sb) * 0.125f + mk[0];
        lg[1] = (a0.y + sb) * 0.125f + mk[1];
        lg[2] = (a0.z + sb) * 0.125f + mk[2];
        lg[3] = (a0.w + sb) * 0.125f + mk[3];
        lg[4] = (a1.x + sb) * 0.125f + mk[4];
        lg[5] = (a1.y + sb) * 0.125f + mk[5];
        lg[6] = (a1.z + sb) * 0.125f + mk[6];
        lg[7] = (a1.w + sb) * 0.125f + mk[7];
        float mx = lg[0];
#pragma unroll
        for (int t = 1; t < 8; t++) mx = fmaxf(mx, lg[t]);
        float m_new = fmaxf(m, mx);
        float p[8], ps = 0.f;
#pragma unroll
        for (int t = 0; t < 8; t++) { p[t] = __expf(lg[t] - m_new); ps += p[t]; }
        float scl = __expf(m - m_new);
        l = l * scl + ps;
        m = m_new;

        // ---- rescale + accumulate weighted x ----
        u64 sclp = pack2(scl, scl);
#pragma unroll
        for (int i = 0; i < 8; i++) fmul2(acc[i], sclp);
#pragma unroll
        for (int t = 0; t < TTILE; t++) {
            const u64* xp = (const u64*)(xbase + t * DM);
            u64 pv = pack2(p[t], p[t]);
#pragma unroll
            for (int i = 0; i < 8; i++) ffma2(acc[i], pv, xp[i]);
        }
        // no trailing sync needed: next prefetch is issued only after the
        // NEXT scores-barrier, by which time all lanes have left this buffer
    }

    float inv = 1.0f / l;
    float* cpo = &g_c[((long)b * 8 + h) * 512 + w * 64 + g * 16];
#pragma unroll
    for (int i = 0; i < 4; i++) {
        float2 v0 = unpack2(acc[2 * i + 0]);
        float2 v1 = unpack2(acc[2 * i + 1]);
        float4 o = make_float4(v0.x * inv, v0.y * inv, v1.x * inv, v1.y * inv);
        *(float4*)(cpo + 4 * i) = o;
    }
}

// ============================================================================
// Kernel D: out[b, h*64+d] = sum_j c[b,h,j] * Wv[h*64+d, j] + bv  (NT, per head)
// 32b x 64d tiles, grid 256.
// ============================================================================
__global__ void __launch_bounds__(256) k_oproj(
    const float* __restrict__ Wv, const float* __restrict__ bv,
    float* __restrict__ out)
{
    __shared__ __align__(16) float Cs[32][64];
    __shared__ __align__(16) float Ws[64][68];   // transposed [j][d]
    const int tid = threadIdx.x;
    const int bB = blockIdx.x * 32;
    const int h  = blockIdx.y;
    const int d0 = (tid & 15) * 4;
    const int b0 = (tid >> 4) * 2;

    u64 acc[2][2];
#pragma unroll
    for (int a = 0; a < 2; a++) { acc[a][0] = 0ull; acc[a][1] = 0ull; }

    for (int jc = 0; jc < 8; jc++) {
#pragma unroll
        for (int it = 0; it < 2; it++) {
            int idx = tid + 256 * it;
            int r = idx >> 4, c4 = (idx & 15) * 4;
            *(float4*)&Cs[r][c4] =
                *(const float4*)&g_c[((long)(bB + r) * 8 + h) * 512 + jc * 64 + c4];
        }
#pragma unroll
        for (int it = 0; it < 4; it++) {
            int idx = tid + 256 * it;
            int r = idx >> 4, c4 = (idx & 15) * 4;
            float4 wv = *(const float4*)&Wv[(h * 64 + r) * 512 + jc * 64 + c4];
            Ws[c4 + 0][r] = wv.x; Ws[c4 + 1][r] = wv.y;
            Ws[c4 + 2][r] = wv.z; Ws[c4 + 3][r] = wv.w;
        }
        __syncthreads();
#pragma unroll
        for (int j = 0; j < 64; j++) {
            ulonglong2 w2 = *(const ulonglong2*)&Ws[j][d0];
#pragma unroll
            for (int cb = 0; cb < 2; cb++) {
                float x = Cs[b0 + cb][j];
                u64 xx = pack2(x, x);
                ffma2(acc[cb][0], xx, w2.x);
                ffma2(acc[cb][1], xx, w2.y);
            }
        }
        __syncthreads();
    }
    float4 bvv = *(const float4*)&bv[h * 64 + d0];
#pragma unroll
    for (int cb = 0; cb < 2; cb++) {
        float2 p0 = unpack2(acc[cb][0]), p1 = unpack2(acc[cb][1]);
        float4 o = make_float4(p0.x + bvv.x, p0.y + bvv.y, p1.x + bvv.z, p1.y + bvv.w);
        *(float4*)&out[(bB + b0 + cb) * 512 + h * 64 + d0] = o;
    }
}

// ============================================================================
extern "C" void kernel_launch(void* const* d_in, const int* in_sizes, int n_in,
                              void* d_out, int out_size)
{
    const float* cur  = (const float*)d_in[0];   // [1024, 512]
    const float* prev = (const float*)d_in[1];   // [1024, 199, 512]
    const float* mask = (const float*)d_in[2];   // [1024, 200]
    const float* Wq   = (const float*)d_in[3];   // [512, 512]
    const float* bq   = (const float*)d_in[4];   // [512]
    const float* Wk   = (const float*)d_in[5];   // [512, 512]
    const float* bk   = (const float*)d_in[6];   // [512]
    const float* Wv   = (const float*)d_in[7];   // [512, 512]
    const float* bv   = (const float*)d_in[8];   // [512]
    float* out = (float*)d_out;                  // [1024, 512]

    k_qproj<<<dim3(32, 8), 256>>>(cur, Wq, bq);
    k_rproj<<<dim3(4, 32, 8), 256>>>(Wk);
    k_attn <<<dim3(1024), 256>>>(cur, prev, mask, bk);
    k_oproj<<<dim3(32, 8), 256>>>(Wv, bv, out);
}

// round 7
// speedup vs baseline: 1.5402x; 1.5402x over previous
#include <cuda_runtime.h>
#include <math_constants.h>

#define BS   1024
#define DM   512
#define NH   8
#define DK   64
#define HIST 199
#define TT   200
#define TTILE 4
#define NBUF 4
#define NTILES 50

// Scratch (static device allocation is allowed).
// NOTE: these symbols are referenced ONLY inside device code. Passing them as
// kernel arguments from host code silently passes the host shadow address
// (ATS makes it dereferenceable -> garbage, no crash). That was R6's bug.
__device__ float g_q[BS * DM];        // 2 MB
__device__ float g_r[BS * NH * DM];   // 16 MB
__device__ float g_c[BS * NH * DM];   // 16 MB

typedef unsigned long long u64;

// ---- packed f32x2 helpers --------------------------------------------------
__device__ __forceinline__ u64 pack2(float x, float y) {
    u64 r; asm("mov.b64 %0, {%1, %2};" : "=l"(r) : "f"(x), "f"(y)); return r;
}
__device__ __forceinline__ float2 unpack2(u64 v) {
    float2 d; asm("mov.b64 {%0, %1}, %2;" : "=f"(d.x), "=f"(d.y) : "l"(v)); return d;
}
__device__ __forceinline__ void ffma2(u64& acc, u64 a, u64 b) {
    asm("fma.rn.f32x2 %0, %1, %2, %0;" : "+l"(acc) : "l"(a), "l"(b));
}
__device__ __forceinline__ void fmul2(u64& a, u64 b) {
    asm("mul.rn.f32x2 %0, %0, %1;" : "+l"(a) : "l"(b));
}
__device__ __forceinline__ void cp16(void* smem_dst, const void* gsrc) {
    unsigned s = (unsigned)__cvta_generic_to_shared(smem_dst);
    asm volatile("cp.async.cg.shared.global [%0], [%1], 16;" :: "r"(s), "l"(gsrc));
}
__device__ __forceinline__ void cp_commit() { asm volatile("cp.async.commit_group;" ::: "memory"); }
__device__ __forceinline__ void cp_wait2()  { asm volatile("cp.async.wait_group 2;" ::: "memory"); }
__device__ __forceinline__ void cp_wait1()  { asm volatile("cp.async.wait_group 1;" ::: "memory"); }

// ============================================================================
// Kernel G: 32b x 64d NT GEMM, contiguous contraction K=512.
// QPROJ=true : out(g_q)[b, y*64+d] = sum_k cur[b,k]          * B[(y*64+d)*512+k] + bias
// QPROJ=false: out(ext)[b, y*64+d] = sum_k g_c[b*4096+y*512+k]* B[(y*64+d)*512+k] + bias
// cp.async double-buffered, fma2 over k-pairs, XOR-swizzled smem.
// ============================================================================
__device__ __forceinline__ int swz(int cj, int row) { return 4 * (cj ^ ((row >> 1) & 7)); }

template<bool QPROJ>
__global__ void __launch_bounds__(256) k_gemm64(
    const float* __restrict__ Aext, const float* __restrict__ B,
    const float* __restrict__ bias, float* __restrict__ outext)
{
    __shared__ __align__(16) float Cs[2][32][32];   // 8 KB
    __shared__ __align__(16) float Ws[2][64][32];   // 16 KB
    const int tid = threadIdx.x;
    const int bB = blockIdx.x * 32;
    const int y  = blockIdx.y;
    const float* Bb = B + (long)y * 64 * 512;
    const int d0 = (tid >> 4) * 4;        // 0..60
    const int b0 = (tid & 15) * 2;        // 0..30

    // A row base resolver (device-side symbol access)
    const float* Abase = QPROJ ? Aext : (const float*)g_c;
    const long a_rstride = QPROJ ? 512 : 4096;
    const long a_yoff    = QPROJ ? 0   : (long)y * 512;

    u64 acc[2][4];
#pragma unroll
    for (int cb = 0; cb < 2; cb++)
#pragma unroll
        for (int dd = 0; dd < 4; dd++) acc[cb][dd] = 0ull;

    {
        int row = tid >> 3, cj = tid & 7;
        cp16(&Cs[0][row][swz(cj, row)],
             Abase + (long)(bB + row) * a_rstride + a_yoff + cj * 4);
    }
#pragma unroll
    for (int i = 0; i < 2; i++) {
        int idx = tid + 256 * i;
        int d = idx >> 3, cj = idx & 7;
        cp16(&Ws[0][d][swz(cj, d)], Bb + (long)d * 512 + cj * 4);
    }
    cp_commit();

    for (int kc = 0; kc < 16; kc++) {
        const int buf = kc & 1;
        if (kc + 1 < 16) {
            {
                int row = tid >> 3, cj = tid & 7;
                cp16(&Cs[buf ^ 1][row][swz(cj, row)],
                     Abase + (long)(bB + row) * a_rstride + a_yoff + (kc + 1) * 32 + cj * 4);
            }
#pragma unroll
            for (int i = 0; i < 2; i++) {
                int idx = tid + 256 * i;
                int d = idx >> 3, cj = idx & 7;
                cp16(&Ws[buf ^ 1][d][swz(cj, d)],
                     Bb + (long)d * 512 + (kc + 1) * 32 + cj * 4);
            }
        }
        cp_commit();                       // always: uniform group count
        cp_wait1();                        // chunk kc complete
        __syncthreads();

#pragma unroll
        for (int jg = 0; jg < 8; jg++) {
            ulonglong2 wv[4], cv[2];
#pragma unroll
            for (int dd = 0; dd < 4; dd++)
                wv[dd] = *(const ulonglong2*)&Ws[buf][d0 + dd][swz(jg, d0 + dd)];
#pragma unroll
            for (int cb = 0; cb < 2; cb++)
                cv[cb] = *(const ulonglong2*)&Cs[buf][b0 + cb][swz(jg, b0 + cb)];
#pragma unroll
            for (int cb = 0; cb < 2; cb++)
#pragma unroll
                for (int dd = 0; dd < 4; dd++) {
                    ffma2(acc[cb][dd], cv[cb].x, wv[dd].x);
                    ffma2(acc[cb][dd], cv[cb].y, wv[dd].y);
                }
        }
        __syncthreads();                   // protect computed buf before reuse
    }

    float* Out = QPROJ ? (float*)g_q : outext;
    float4 bb = *(const float4*)&bias[y * 64 + d0];
#pragma unroll
    for (int cb = 0; cb < 2; cb++) {
        float v[4];
#pragma unroll
        for (int dd = 0; dd < 4; dd++) {
            float2 u = unpack2(acc[cb][dd]);
            v[dd] = u.x + u.y;
        }
        float4 o = make_float4(v[0] + bb.x, v[1] + bb.y, v[2] + bb.z, v[3] + bb.w);
        *(float4*)&Out[(long)(bB + b0 + cb) * 512 + y * 64 + d0] = o;
    }
}

// ============================================================================
// Kernel B: r[b,h,n] = sum_k q[b, h*64+k] * Wk[h*64+k, n]   (NN, K=64)
// ============================================================================
__global__ void __launch_bounds__(256) k_rproj(const float* __restrict__ Wk)
{
    __shared__ __align__(16) float Wks[64][128];
    __shared__ __align__(16) float qs[32][64];
    const int tid = threadIdx.x;
    const int nc = blockIdx.x;           // 0..3  (n chunk of 128)
    const int bB = blockIdx.y * 32;      // 0..31 (b tile of 32)
    const int h  = blockIdx.z;           // 0..7

#pragma unroll
    for (int it = 0; it < 8; it++) {
        int idx = tid + 256 * it;        // 2048 float4
        int k = idx >> 5, n4 = (idx & 31) * 4;
        *(float4*)&Wks[k][n4] = *(const float4*)&Wk[(h * 64 + k) * 512 + nc * 128 + n4];
    }
#pragma unroll
    for (int it = 0; it < 2; it++) {
        int idx = tid + 256 * it;        // 512 float4
        int bb = idx >> 4, k4 = (idx & 15) * 4;
        *(float4*)&qs[bb][k4] = *(const float4*)&g_q[(bB + bb) * 512 + h * 64 + k4];
    }
    __syncthreads();

    const int n0 = (tid & 31) * 4;
    const int b0 = (tid >> 5) * 4;
    u64 acc[4][2];
#pragma unroll
    for (int a = 0; a < 4; a++) { acc[a][0] = 0ull; acc[a][1] = 0ull; }

#pragma unroll
    for (int k = 0; k < 64; k++) {
        ulonglong2 w2 = *(const ulonglong2*)&Wks[k][n0];
#pragma unroll
        for (int cb = 0; cb < 4; cb++) {
            float x = qs[b0 + cb][k];
            u64 xx = pack2(x, x);
            ffma2(acc[cb][0], xx, w2.x);
            ffma2(acc[cb][1], xx, w2.y);
        }
    }
#pragma unroll
    for (int cb = 0; cb < 4; cb++) {
        float2 p0 = unpack2(acc[cb][0]), p1 = unpack2(acc[cb][1]);
        float4 o = make_float4(p0.x, p0.y, p1.x, p1.y);
        *(float4*)&g_r[((bB + b0 + cb) * 8 + h) * 512 + nc * 128 + n0] = o;
    }
}

// ============================================================================
// Kernel C: streaming attention, online softmax, 4-deep cp.async pipeline.
// 1 CTA / batch row, 256 thr. Warp w owns j-slice [w*64, w*64+64); lane
// (h = lane>>2, g = lane&3) owns chunks {w*64 + g*4 + 16c + 0..3, c=0..3}
// (16-float-strided float4s -> every smem access is one conflict-free LDS.128).
// ============================================================================
__device__ __forceinline__ void prefetch_tile(
    float* dst, const float* __restrict__ prev, const float* __restrict__ cur,
    int b, int tile, int tid)
{
#pragma unroll
    for (int i = 0; i < 2; i++) {
        int idx = tid + 256 * i;        // 512 float4 = 4 rows x 512 floats
        int tr = idx >> 7;
        int c = (idx & 127) * 4;
        int gt = tile * TTILE + tr;
        const float* src = (gt < HIST)
            ? (prev + ((long)b * HIST + gt) * 512 + c)
            : (cur + (long)b * 512 + c);
        cp16(dst + tr * 512 + c, src);
    }
}

__global__ void __launch_bounds__(256) k_attn(
    const float* __restrict__ cur, const float* __restrict__ prev,
    const float* __restrict__ mask, const float* __restrict__ bk)
{
    __shared__ __align__(16) float xb[NBUF][TTILE][DM];   // 32 KB
    __shared__ __align__(16) float s_part[8][8][TTILE];   // 1 KB
    __shared__ float mask_s[TT];
    __shared__ float sb_s[8];

    const int tid = threadIdx.x;
    const int b = blockIdx.x;
    const int w = tid >> 5, lane = tid & 31;
    const int h = lane >> 2, g = lane & 3;

    if (tid < TT) mask_s[tid] = mask[b * TT + tid];
    {   // sb[h] = q[b,h,:]·bk[h,:]; warp w handles head w
        float q1 = g_q[b * 512 + w * 64 + lane];
        float q2 = g_q[b * 512 + w * 64 + 32 + lane];
        float s = q1 * bk[w * 64 + lane] + q2 * bk[w * 64 + 32 + lane];
#pragma unroll
        for (int o = 16; o; o >>= 1) s += __shfl_xor_sync(0xffffffffu, s, o);
        if (lane == 0) sb_s[w] = s;
    }

    // r fragment: 4 strided float4 chunks (matches x-access mapping)
    u64 rf[8];
    {
        const float* rp = &g_r[(long)b * 4096 + h * 512 + w * 64 + g * 4];
#pragma unroll
        for (int c = 0; c < 4; c++) {
            ulonglong2 v = *(const ulonglong2*)(rp + 16 * c);
            rf[2 * c + 0] = v.x;
            rf[2 * c + 1] = v.y;
        }
    }
    u64 acc[8];
#pragma unroll
    for (int i = 0; i < 8; i++) acc[i] = 0ull;
    float m = -CUDART_INF_F, l = 0.f;

    // prime 3 tiles
#pragma unroll
    for (int i = 0; i < 3; i++) {
        prefetch_tile(&xb[i][0][0], prev, cur, b, i, tid);
        cp_commit();
    }
    __syncthreads();                       // sb_s / mask_s visible
    const float sb = sb_s[h];

    for (int tile = 0; tile < NTILES; tile++) {
        const int buf = tile & (NBUF - 1);
        cp_wait2();                        // tile's group complete (3 in flight)
        __syncthreads();

        const float* xbase = &xb[buf][0][w * 64 + g * 4];
        // ---- partial scores ----
#pragma unroll
        for (int t = 0; t < TTILE; t++) {
            const float* xr = xbase + t * DM;
            ulonglong2 x0 = *(const ulonglong2*)(xr);
            ulonglong2 x1 = *(const ulonglong2*)(xr + 16);
            ulonglong2 x2 = *(const ulonglong2*)(xr + 32);
            ulonglong2 x3 = *(const ulonglong2*)(xr + 48);
            u64 sa = 0ull, sc = 0ull;
            ffma2(sa, rf[0], x0.x); ffma2(sc, rf[1], x0.y);
            ffma2(sa, rf[2], x1.x); ffma2(sc, rf[3], x1.y);
            ffma2(sa, rf[4], x2.x); ffma2(sc, rf[5], x2.y);
            ffma2(sa, rf[6], x3.x); ffma2(sc, rf[7], x3.y);
            float2 fa = unpack2(sa), fc = unpack2(sc);
            float s = (fa.x + fa.y) + (fc.x + fc.y);
            s += __shfl_xor_sync(0xffffffffu, s, 1);
            s += __shfl_xor_sync(0xffffffffu, s, 2);
            if (g == 0) s_part[w][h][t] = s;
        }
        __syncthreads();                   // s_part complete; accumulate(tile-1) done CTA-wide

        // keep the pipeline fed (buffer (tile+3)&3 == (tile-1)&3, now free)
        if (tile + 3 < NTILES)
            prefetch_tile(&xb[(tile + 3) & (NBUF - 1)][0][0], prev, cur, b, tile + 3, tid);
        cp_commit();                       // always (empty groups at tail keep count)

        // ---- per-lane replicated online softmax for head h ----
        float4 a0 = make_float4(0.f, 0.f, 0.f, 0.f);
#pragma unroll
        for (int w2 = 0; w2 < 8; w2++) {
            float4 v = *(const float4*)&s_part[w2][h][0];
            a0.x += v.x; a0.y += v.y; a0.z += v.z; a0.w += v.w;
        }
        const float* mk = &mask_s[tile * TTILE];
        float lg[4];
        lg[0] = (a0.x + sb) * 0.125f + mk[0];
        lg[1] = (a0.y + sb) * 0.125f + mk[1];
        lg[2] = (a0.z + sb) * 0.125f + mk[2];
        lg[3] = (a0.w + sb) * 0.125f + mk[3];
        float mx = fmaxf(fmaxf(lg[0], lg[1]), fmaxf(lg[2], lg[3]));
        float m_new = fmaxf(m, mx);
        float p[4], ps = 0.f;
#pragma unroll
        for (int t = 0; t < 4; t++) { p[t] = __expf(lg[t] - m_new); ps += p[t]; }
        float scl = __expf(m - m_new);
        l = l * scl + ps;
        m = m_new;

        // ---- rescale + accumulate weighted x ----
        u64 sclp = pack2(scl, scl);
#pragma unroll
        for (int i = 0; i < 8; i++) fmul2(acc[i], sclp);
#pragma unroll
        for (int t = 0; t < TTILE; t++) {
            const float* xr = xbase + t * DM;
            ulonglong2 x0 = *(const ulonglong2*)(xr);
            ulonglong2 x1 = *(const ulonglong2*)(xr + 16);
            ulonglong2 x2 = *(const ulonglong2*)(xr + 32);
            ulonglong2 x3 = *(const ulonglong2*)(xr + 48);
            u64 pv = pack2(p[t], p[t]);
            ffma2(acc[0], pv, x0.x); ffma2(acc[1], pv, x0.y);
            ffma2(acc[2], pv, x1.x); ffma2(acc[3], pv, x1.y);
            ffma2(acc[4], pv, x2.x); ffma2(acc[5], pv, x2.y);
            ffma2(acc[6], pv, x3.x); ffma2(acc[7], pv, x3.y);
        }
    }

    float inv = 1.0f / l;
    float* cpo = &g_c[((long)b * 8 + h) * 512 + w * 64 + g * 4];
#pragma unroll
    for (int c = 0; c < 4; c++) {
        float2 v0 = unpack2(acc[2 * c + 0]);
        float2 v1 = unpack2(acc[2 * c + 1]);
        float4 o = make_float4(v0.x * inv, v0.y * inv, v1.x * inv, v1.y * inv);
        *(float4*)(cpo + 16 * c) = o;
    }
}

// ============================================================================
extern "C" void kernel_launch(void* const* d_in, const int* in_sizes, int n_in,
                              void* d_out, int out_size)
{
    const float* cur  = (const float*)d_in[0];   // [1024, 512]
    const float* prev = (const float*)d_in[1];   // [1024, 199, 512]
    const float* mask = (const float*)d_in[2];   // [1024, 200]
    const float* Wq   = (const float*)d_in[3];   // [512, 512]
    const float* bq   = (const float*)d_in[4];   // [512]
    const float* Wk   = (const float*)d_in[5];   // [512, 512]
    const float* bk   = (const float*)d_in[6];   // [512]
    const float* Wv   = (const float*)d_in[7];   // [512, 512]
    const float* bv   = (const float*)d_in[8];   // [512]
    float* out = (float*)d_out;                  // [1024, 512]

    // q = cur @ Wq^T + bq          (writes g_q internally)
    k_gemm64<true ><<<dim3(32, 8), 256>>>(cur, Wq, bq, nullptr);
    // r[b,h,:] = Wk_h^T q_h        (g_q -> g_r)
    k_rproj<<<dim3(4, 32, 8), 256>>>(Wk);
    // streaming attention over raw embeddings (-> g_c)
    k_attn <<<dim3(1024), 256>>>(cur, prev, mask, bk);
    // out = c @ Wv_h^T + bv        (reads g_c internally)
    k_gemm64<false><<<dim3(32, 8), 256>>>(nullptr, Wv, bv, out);
}